// round 9
// baseline (speedup 1.0000x reference)
#include <cuda_runtime.h>
#include <cstdint>

#define NN 8192
#define FF 64
#define OO 64
#define BM 128
#define BK2 32
#define SPLITK 4
#define KHALF (NN / SPLITK)    // 2048
#define NT (KHALF / BK2)       // 64 tiles per CTA

#define AW 20                       // 32-bit words per smem row (16 data + 4 pad)
#define A_WORDS (BM * AW)           // 2560
#define B_WORDS (64 * AW)           // 1280
#define STG_WORDS (A_WORDS + B_WORDS)     // 3840 words
#define STG_BYTES (STG_WORDS * 4)         // 15360
#define A_BYTES_OFF (A_WORDS * 4)         // 10240
#define SMEM_MAIN (3 * STG_BYTES)         // 46080

// -------------------- scratch --------------------
__device__ uint16_t g_YTh[64 * NN];      // bf16 YT[n][k] = (X @ W2^T)[k][n]
__device__ float g_XW1[NN * OO];         // X @ W1^T
__device__ float g_T[SPLITK][NN * OO];   // split-K partials of A @ YT^T
__device__ float g_degp[SPLITK][NN];     // split-K partials of rowsum(A)

__device__ __forceinline__ uint32_t smem_u32(const void* p) {
    uint32_t a;
    asm("{ .reg .u64 t; cvta.to.shared.u64 t, %1; cvt.u32.u64 %0, t; }" : "=r"(a) : "l"(p));
    return a;
}
__device__ __forceinline__ void mma_bf16(float* c, uint32_t a0, uint32_t a1, uint32_t a2,
                                         uint32_t a3, uint32_t b0, uint32_t b1) {
    asm volatile(
        "mma.sync.aligned.m16n8k16.row.col.f32.bf16.bf16.f32 "
        "{%0,%1,%2,%3}, {%4,%5,%6,%7}, {%8,%9}, {%0,%1,%2,%3};\n"
        : "+f"(c[0]), "+f"(c[1]), "+f"(c[2]), "+f"(c[3])
        : "r"(a0), "r"(a1), "r"(a2), "r"(a3), "r"(b0), "r"(b1));
}
#define CVT2(d, hi, lo) \
    asm("cvt.rn.bf16x2.f32 %0, %1, %2;" : "=r"(d) : "f"(hi), "f"(lo))
#define LDSM4(r0, r1, r2, r3, addr)                                              \
    asm volatile("ldmatrix.sync.aligned.m8n8.x4.shared.b16 {%0,%1,%2,%3}, [%4];" \
                 : "=r"(r0), "=r"(r1), "=r"(r2), "=r"(r3) : "r"(addr))

// ===================== kernel 1: projections (16 rows/block, grid 512) ==========
#define WST_STRIDE 136
#define XST_STRIDE 17
#define YS_STRIDE  66
#define PROJ_SMEM ((64 * WST_STRIDE + 64 * XST_STRIDE + 16 * YS_STRIDE) * 4)

__global__ __launch_bounds__(256) void proj_kernel(const float* __restrict__ x,
                                                   const float* __restrict__ W) {
    extern __shared__ float s[];
    float* Wst = s;                          // Wst[k][n] = W[n&63][(n>>6)*64 + k]
    float* xst = Wst + 64 * WST_STRIDE;      // xst[k][r] = x[i0+r][k]
    float* ys  = xst + 64 * XST_STRIDE;      // ys[r][q]  = Y[i0+r][q]

    const int t  = threadIdx.x;
    const int i0 = blockIdx.x * 16;

#pragma unroll
    for (int j = 0; j < 32; ++j) {
        int idx = t + j * 256;               // 0..8191
        int o = idx >> 7, c = idx & 127;
        Wst[(c & 63) * WST_STRIDE + (c >> 6) * 64 + o] = W[idx];
    }
#pragma unroll
    for (int j = 0; j < 4; ++j) {
        int idx = t + j * 256;               // 0..1023
        int r = idx >> 6, k = idx & 63;
        xst[k * XST_STRIDE + r] = x[(size_t)(i0 + r) * FF + k];
    }
    __syncthreads();

    const int tx = t & 15;                   // col group tx*8
    const int ty = t >> 4;                   // row ty (0..15)

    float acc[8];
#pragma unroll
    for (int j = 0; j < 8; ++j) acc[j] = 0.0f;

#pragma unroll
    for (int k = 0; k < 64; ++k) {
        float a   = xst[k * XST_STRIDE + ty];
        float4 b0 = *(const float4*)&Wst[k * WST_STRIDE + tx * 8];
        float4 b1 = *(const float4*)&Wst[k * WST_STRIDE + tx * 8 + 4];
        acc[0] = fmaf(a, b0.x, acc[0]); acc[1] = fmaf(a, b0.y, acc[1]);
        acc[2] = fmaf(a, b0.z, acc[2]); acc[3] = fmaf(a, b0.w, acc[3]);
        acc[4] = fmaf(a, b1.x, acc[4]); acc[5] = fmaf(a, b1.y, acc[5]);
        acc[6] = fmaf(a, b1.z, acc[6]); acc[7] = fmaf(a, b1.w, acc[7]);
    }

    if (tx < 8) {
        size_t base = (size_t)(i0 + ty) * OO + tx * 8;
        *(float4*)&g_XW1[base]     = make_float4(acc[0], acc[1], acc[2], acc[3]);
        *(float4*)&g_XW1[base + 4] = make_float4(acc[4], acc[5], acc[6], acc[7]);
    } else {
        int qb = (tx - 8) * 8;
#pragma unroll
        for (int j = 0; j < 8; ++j) ys[ty * YS_STRIDE + qb + j] = acc[j];
    }
    __syncthreads();

    // YT write: col = t&63 (n), rows rb..rb+3 (k dim), packed bf16
    {
        int col = t & 63, rb = (t >> 6) * 4;
        float v0 = ys[(rb + 0) * YS_STRIDE + col];
        float v1 = ys[(rb + 1) * YS_STRIDE + col];
        float v2 = ys[(rb + 2) * YS_STRIDE + col];
        float v3 = ys[(rb + 3) * YS_STRIDE + col];
        uint32_t u0, u1;
        CVT2(u0, v1, v0);
        CVT2(u1, v3, v2);
        *(uint2*)&g_YTh[(size_t)col * NN + i0 + rb] = make_uint2(u0, u1);
    }
}

// ===================== kernel 2: split-K A@Y, bf16 + ldmatrix =====================
#define LDG_A(buf, t_) do {                                                        \
    int k0 = (t_) * BK2;                                                           \
    _Pragma("unroll")                                                              \
    for (int i_ = 0; i_ < 4; ++i_) {                                               \
        int idx = tid + i_ * 256;                                                  \
        buf[i_] = *(const float4*)(Abase + (size_t)(idx >> 3) * NN + k0 + (idx & 7) * 4); \
    }                                                                              \
} while (0)

#define STS_A(buf, st) do {                                                        \
    uint2* base = (uint2*)(sm + (st) * STG_WORDS);                                 \
    _Pragma("unroll")                                                              \
    for (int i_ = 0; i_ < 4; ++i_) {                                               \
        float4 v = buf[i_];                                                        \
        int idx = tid + i_ * 256;                                                  \
        dsum[i_] += (v.x + v.y) + (v.z + v.w);                                     \
        uint32_t lo, hi;                                                           \
        CVT2(lo, v.y, v.x); CVT2(hi, v.w, v.z);                                    \
        base[(idx >> 3) * 10 + (idx & 7)] = make_uint2(lo, hi);                    \
    }                                                                              \
} while (0)

#define CPA_B(st, t_) do {                                                         \
    int k0 = (t_) * BK2;                                                           \
    int n_ = tid >> 2, c_ = tid & 3;                                               \
    uint32_t dst = smemU + (st) * STG_BYTES + A_BYTES_OFF + n_ * 80 + c_ * 16;     \
    const uint16_t* src = Bbase + (size_t)n_ * NN + k0 + c_ * 8;                   \
    asm volatile("cp.async.cg.shared.global [%0], [%1], 16;\n" :: "r"(dst), "l"(src)); \
} while (0)

#define MMA_STAGE(st) do {                                                         \
    uint32_t aB = aAddr + (st) * STG_BYTES;                                        \
    uint32_t bB = bAddr + (st) * STG_BYTES;                                        \
    _Pragma("unroll")                                                              \
    for (int s_ = 0; s_ < 2; ++s_) {                                               \
        uint32_t a[2][4], bb[8];                                                   \
        LDSM4(a[0][0], a[0][1], a[0][2], a[0][3], aB + s_ * 32);                   \
        LDSM4(a[1][0], a[1][1], a[1][2], a[1][3], aB + s_ * 32 + 1280);            \
        LDSM4(bb[0], bb[1], bb[2], bb[3], bB + s_ * 32);                           \
        LDSM4(bb[4], bb[5], bb[6], bb[7], bB + s_ * 32 + 1280);                    \
        _Pragma("unroll")                                                          \
        for (int h_ = 0; h_ < 2; ++h_)                                             \
            _Pragma("unroll")                                                      \
            for (int t_ = 0; t_ < 4; ++t_)                                         \
                mma_bf16(acc[h_][t_], a[h_][0], a[h_][1], a[h_][2], a[h_][3],      \
                         bb[t_ * 2], bb[t_ * 2 + 1]);                              \
    }                                                                              \
} while (0)

#define BODY(i_, BUFX, BUFY) do {                                                  \
    if ((i_) + 2 < NT) LDG_A(BUFX, (i_) + 2);                                      \
    asm volatile("cp.async.wait_group 1;\n" ::: "memory");                         \
    __syncthreads();                                                               \
    if ((i_) + 2 < NT) CPA_B(((i_) + 2) % 3, (i_) + 2);                            \
    asm volatile("cp.async.commit_group;\n" ::: "memory");                         \
    MMA_STAGE((i_) % 3);                                                           \
    if ((i_) + 1 < NT) STS_A(BUFY, ((i_) + 1) % 3);                                \
} while (0)

__global__ __launch_bounds__(256, 2) void sage_mma_kernel(const float* __restrict__ A) {
    extern __shared__ uint32_t sm[];
    const uint32_t smemU = smem_u32(sm);
    const int tid  = threadIdx.x;
    const int wid  = tid >> 5;
    const int lane = tid & 31;
    const int grp  = lane >> 2;       // 0..7
    const int kq   = lane & 3;        // 0..3
    const int mw   = wid & 3;         // m-stripe: rows mw*32..mw*32+31
    const int nh   = wid >> 2;        // n-half: n-tiles nh*4..nh*4+3

    const int mtile = blockIdx.x >> 2;       // 0..63
    const int kh    = blockIdx.x & 3;        // 0..3
    const float* Abase = A + (size_t)mtile * BM * NN + (size_t)kh * KHALF;
    const uint16_t* Bbase = g_YTh + (size_t)kh * KHALF;

    // ldmatrix per-warp base addresses
    const uint32_t aAddr = smemU + (mw * 32 + (lane & 15)) * 80 + (lane >> 4) * 16;
    const uint32_t bAddr = smemU + A_BYTES_OFF +
        (nh * 32 + ((lane >> 4) & 1) * 8 + (lane & 7)) * 80 + ((lane >> 3) & 1) * 16;

    float acc[2][4][4];
#pragma unroll
    for (int h = 0; h < 2; ++h)
#pragma unroll
        for (int t = 0; t < 4; ++t)
#pragma unroll
            for (int r = 0; r < 4; ++r) acc[h][t][r] = 0.0f;
    float dsum[4] = {0.f, 0.f, 0.f, 0.f};

    float4 buf1[4], buf2[4];

    // prolog
    LDG_A(buf1, 0);
    CPA_B(0, 0);
    asm volatile("cp.async.commit_group;\n" ::: "memory");
    STS_A(buf1, 0);
    LDG_A(buf2, 1);
    CPA_B(1, 1);
    asm volatile("cp.async.commit_group;\n" ::: "memory");

    for (int i = 0; i < NT; i += 2) {
        BODY(i,     buf1, buf2);
        BODY(i + 1, buf2, buf1);
    }

    // deg partials: rows (tid>>3)+32*i, 8 chunk-threads per row
#pragma unroll
    for (int i = 0; i < 4; ++i) {
        float d = dsum[i];
        d += __shfl_down_sync(0xFFFFFFFFu, d, 4);
        d += __shfl_down_sync(0xFFFFFFFFu, d, 2);
        d += __shfl_down_sync(0xFFFFFFFFu, d, 1);
        if ((lane & 7) == 0)
            g_degp[kh][mtile * BM + (tid >> 3) + i * 32] = d;
    }

    // store partial T
    float* dst = g_T[kh];
#pragma unroll
    for (int h = 0; h < 2; ++h) {
        int row_lo = mtile * BM + mw * 32 + h * 16 + grp;
        int row_hi = row_lo + 8;
#pragma unroll
        for (int t = 0; t < 4; ++t) {
            int col = (nh * 4 + t) * 8 + 2 * kq;
            *(float2*)&dst[(size_t)row_lo * OO + col] = make_float2(acc[h][t][0], acc[h][t][1]);
            *(float2*)&dst[(size_t)row_hi * OO + col] = make_float2(acc[h][t][2], acc[h][t][3]);
        }
    }
}

// ===================== kernel 3: combine + epilogue =====================
__global__ __launch_bounds__(256) void epilogue_kernel(float* __restrict__ out) {
    int idx = blockIdx.x * blockDim.x + threadIdx.x;   // r*64 + c
    int r = idx >> 6;
    float deg = 1.0f, t = 0.0f;
#pragma unroll
    for (int s = 0; s < SPLITK; ++s) {
        deg += g_degp[s][r];
        t   += g_T[s][idx];
    }
    out[idx] = g_XW1[idx] + t / deg;
}

// -------------------- launch --------------------
extern "C" void kernel_launch(void* const* d_in, const int* in_sizes, int n_in,
                              void* d_out, int out_size) {
    const float* adj      = (const float*)d_in[0];  // [8192, 8192]
    const float* features = (const float*)d_in[1];  // [8192, 64]
    const float* W        = (const float*)d_in[2];  // [64, 128]
    float* out            = (float*)d_out;          // [8192, 64]

    cudaFuncSetAttribute(proj_kernel,
                         cudaFuncAttributeMaxDynamicSharedMemorySize, PROJ_SMEM);
    cudaFuncSetAttribute(sage_mma_kernel,
                         cudaFuncAttributeMaxDynamicSharedMemorySize, SMEM_MAIN);

    proj_kernel<<<NN / 16, 256, PROJ_SMEM>>>(features, W);
    sage_mma_kernel<<<SPLITK * (NN / BM), 256, SMEM_MAIN>>>(adj);
    epilogue_kernel<<<(NN * OO) / 256, 256>>>(out);
}

// round 10
// speedup vs baseline: 1.3722x; 1.3722x over previous
#include <cuda_runtime.h>
#include <cstdint>

#define NN 8192
#define FF 64
#define OO 64
#define BM 128
#define SPLITK 4
#define KH (NN / SPLITK)      // 2048
#define NT (KH / 32)          // 64 k-tiles per CTA
#define PD 4                  // B prefetch distance
#define NSTG 5                // B smem stages
#define BROW 20               // words per B smem row (16 data + 4 pad = 80B)
#define BSTG_W (64 * BROW)    // words per stage = 1280
#define BSTG_B (BSTG_W * 4)   // 5120 B
#define SMEM_MAIN (NSTG * BSTG_B)   // 25600 B

// -------------------- scratch --------------------
__device__ uint16_t g_YTh[64 * NN];      // bf16 YT[n][k] = (X @ W2^T)[k][n]
__device__ float g_Wt[64 * 128];         // Wt[k][n] = W[n&63][(n>>6)*64 + k]
__device__ float g_XW1[NN * OO];         // X @ W1^T
__device__ float g_T[SPLITK][NN * OO];   // split-K partials of A @ YT^T
__device__ float g_degp[SPLITK][NN];     // split-K partials of rowsum(A)

__device__ __forceinline__ uint32_t smem_u32(const void* p) {
    uint32_t a;
    asm("{ .reg .u64 t; cvta.to.shared.u64 t, %1; cvt.u32.u64 %0, t; }" : "=r"(a) : "l"(p));
    return a;
}
__device__ __forceinline__ void mma_bf16(float* c, uint32_t a0, uint32_t a1, uint32_t a2,
                                         uint32_t a3, uint32_t b0, uint32_t b1) {
    asm volatile(
        "mma.sync.aligned.m16n8k16.row.col.f32.bf16.bf16.f32 "
        "{%0,%1,%2,%3}, {%4,%5,%6,%7}, {%8,%9}, {%0,%1,%2,%3};\n"
        : "+f"(c[0]), "+f"(c[1]), "+f"(c[2]), "+f"(c[3])
        : "r"(a0), "r"(a1), "r"(a2), "r"(a3), "r"(b0), "r"(b1));
}
#define CVT2(d, hi, lo) \
    asm("cvt.rn.bf16x2.f32 %0, %1, %2;" : "=r"(d) : "f"(hi), "f"(lo))
#define LDSM4(r0, r1, r2, r3, addr)                                              \
    asm volatile("ldmatrix.sync.aligned.m8n8.x4.shared.b16 {%0,%1,%2,%3}, [%4];" \
                 : "=r"(r0), "=r"(r1), "=r"(r2), "=r"(r3) : "r"(addr))
#define CPA16(dst, src) \
    asm volatile("cp.async.cg.shared.global [%0], [%1], 16;\n" :: "r"(dst), "l"(src))
#define CPCOMMIT() asm volatile("cp.async.commit_group;\n" ::: "memory")
#define CPWAIT(n)  asm volatile("cp.async.wait_group %0;\n" :: "n"(n) : "memory")

// ===================== kernel 0: W pre-transpose (once) =====================
__global__ void prep_w_kernel(const float* __restrict__ W) {
    int idx = blockIdx.x * 256 + threadIdx.x;   // 0..8191
    int o = idx >> 7, c = idx & 127;
    g_Wt[(c & 63) * 128 + (c >> 6) * 64 + o] = W[idx];
}

// ===================== kernel 1: projections (32 rows/block) =====================
#define WST_STRIDE 136
#define XST_STRIDE 34
#define YS_STRIDE  66
#define PROJ_SMEM ((64 * WST_STRIDE + 64 * XST_STRIDE + 32 * YS_STRIDE) * 4)

__global__ __launch_bounds__(256) void proj_kernel(const float* __restrict__ x) {
    extern __shared__ float s[];
    float* Wst = s;                          // Wst[k][n], stride 136
    float* xst = Wst + 64 * WST_STRIDE;      // xst[k][r] = x[i0+r][k]
    float* ys  = xst + 64 * XST_STRIDE;      // ys[r][q]  = Y[i0+r][q]

    const int t  = threadIdx.x;
    const int i0 = blockIdx.x * 32;

    // W copy from pre-transposed g_Wt: coalesced, conflict-free
#pragma unroll
    for (int j = 0; j < 8; ++j) {
        int idx4 = t + j * 256;              // 0..2047 float4s
        int k = idx4 >> 5, n4 = (idx4 & 31) * 4;
        *(float4*)&Wst[k * WST_STRIDE + n4] = *(const float4*)&g_Wt[k * 128 + n4];
    }
#pragma unroll
    for (int j = 0; j < 8; ++j) {
        int idx = t + j * 256;               // 0..2047
        int r = idx >> 6, k = idx & 63;
        xst[k * XST_STRIDE + r] = x[(size_t)(i0 + r) * FF + k];
    }
    __syncthreads();

    const int tx = t & 15;
    const int ty = t >> 4;

    float acc[2][8];
#pragma unroll
    for (int r = 0; r < 2; ++r)
#pragma unroll
        for (int j = 0; j < 8; ++j) acc[r][j] = 0.0f;

#pragma unroll
    for (int k = 0; k < 64; ++k) {
        float2 a  = *(const float2*)&xst[k * XST_STRIDE + 2 * ty];
        float4 b0 = *(const float4*)&Wst[k * WST_STRIDE + tx * 8];
        float4 b1 = *(const float4*)&Wst[k * WST_STRIDE + tx * 8 + 4];
        float av[2] = {a.x, a.y};
        float bv[8] = {b0.x, b0.y, b0.z, b0.w, b1.x, b1.y, b1.z, b1.w};
#pragma unroll
        for (int r = 0; r < 2; ++r)
#pragma unroll
            for (int j = 0; j < 8; ++j) acc[r][j] = fmaf(av[r], bv[j], acc[r][j]);
    }

    if (tx < 8) {
#pragma unroll
        for (int r = 0; r < 2; ++r) {
            size_t base = (size_t)(i0 + 2 * ty + r) * OO + tx * 8;
            *(float4*)&g_XW1[base]     = make_float4(acc[r][0], acc[r][1], acc[r][2], acc[r][3]);
            *(float4*)&g_XW1[base + 4] = make_float4(acc[r][4], acc[r][5], acc[r][6], acc[r][7]);
        }
    } else {
        int qb = (tx - 8) * 8;
#pragma unroll
        for (int r = 0; r < 2; ++r)
#pragma unroll
            for (int j = 0; j < 8; ++j)
                ys[(2 * ty + r) * YS_STRIDE + qb + j] = acc[r][j];
    }
    __syncthreads();

    // YT write: col = t&63 (n), rows rb..rb+7 (k dim), packed bf16 (16B store)
    {
        int col = t & 63, rb = (t >> 6) * 8;
        float v[8];
#pragma unroll
        for (int j = 0; j < 8; ++j) v[j] = ys[(rb + j) * YS_STRIDE + col];
        uint32_t u[4];
        CVT2(u[0], v[1], v[0]);
        CVT2(u[1], v[3], v[2]);
        CVT2(u[2], v[5], v[4]);
        CVT2(u[3], v[7], v[6]);
        *(uint4*)&g_YTh[(size_t)col * NN + i0 + rb] = make_uint4(u[0], u[1], u[2], u[3]);
    }
}

// ===================== kernel 2: split-K A@Y, reg-direct A frags =====================
// fb layout: fb[s*4 + ro*2 + p] = float2 at (row + ro*8, k = s*16 + 2*kq + p*8)
#define LDGA(fb, t_) do {                                                          \
    const float* p_ = Abase + (t_) * 32;                                           \
    fb[0] = *(const float2*)(p_);                                                  \
    fb[1] = *(const float2*)(p_ + 8);                                              \
    fb[2] = *(const float2*)(p_ + 8 * NN);                                         \
    fb[3] = *(const float2*)(p_ + 8 * NN + 8);                                     \
    fb[4] = *(const float2*)(p_ + 16);                                             \
    fb[5] = *(const float2*)(p_ + 24);                                             \
    fb[6] = *(const float2*)(p_ + 8 * NN + 16);                                    \
    fb[7] = *(const float2*)(p_ + 8 * NN + 24);                                    \
} while (0)

// a-frag: af[s][0]=(r,klo) af[s][1]=(r+8,klo) af[s][2]=(r,khi) af[s][3]=(r+8,khi)
#define CVTA(fb) do {                                                              \
    _Pragma("unroll")                                                              \
    for (int s_ = 0; s_ < 2; ++s_) {                                               \
        CVT2(af[s_][0], fb[s_*4+0].y, fb[s_*4+0].x);                               \
        CVT2(af[s_][2], fb[s_*4+1].y, fb[s_*4+1].x);                               \
        CVT2(af[s_][1], fb[s_*4+2].y, fb[s_*4+2].x);                               \
        CVT2(af[s_][3], fb[s_*4+3].y, fb[s_*4+3].x);                               \
        ds0 += (fb[s_*4+0].x + fb[s_*4+0].y) + (fb[s_*4+1].x + fb[s_*4+1].y);      \
        ds1 += (fb[s_*4+2].x + fb[s_*4+2].y) + (fb[s_*4+3].x + fb[s_*4+3].y);      \
    }                                                                              \
} while (0)

#define BODY(i_, FBC, FBN) do {                                                    \
    CPWAIT(3);                                                                     \
    __syncthreads();                                                               \
    if ((i_) + PD < NT) CPA16(bDst + (((i_) + PD) % NSTG) * BSTG_B,                \
                              Bsrc + ((i_) + PD) * 32);                            \
    CPCOMMIT();                                                                    \
    if ((i_) + 1 < NT) LDGA(FBN, (i_) + 1);                                        \
    uint32_t af[2][4];                                                             \
    CVTA(FBC);                                                                     \
    uint32_t stB = ((i_) % NSTG) * BSTG_B;                                         \
    _Pragma("unroll")                                                              \
    for (int s_ = 0; s_ < 2; ++s_) {                                               \
        uint32_t b_[16];                                                           \
        LDSM4(b_[0],  b_[1],  b_[2],  b_[3],  bOff[0] + stB + s_ * 32);            \
        LDSM4(b_[4],  b_[5],  b_[6],  b_[7],  bOff[1] + stB + s_ * 32);            \
        LDSM4(b_[8],  b_[9],  b_[10], b_[11], bOff[2] + stB + s_ * 32);            \
        LDSM4(b_[12], b_[13], b_[14], b_[15], bOff[3] + stB + s_ * 32);            \
        _Pragma("unroll")                                                          \
        for (int nt_ = 0; nt_ < 8; ++nt_)                                          \
            mma_bf16(acc[nt_], af[s_][0], af[s_][1], af[s_][2], af[s_][3],         \
                     b_[(nt_ >> 1) * 4 + (nt_ & 1) * 2],                           \
                     b_[(nt_ >> 1) * 4 + (nt_ & 1) * 2 + 1]);                      \
    }                                                                              \
} while (0)

__global__ __launch_bounds__(256, 2) void sage_mma_kernel(const float* __restrict__ A) {
    extern __shared__ uint32_t sm[];
    const uint32_t smemU = smem_u32(sm);
    const int tid  = threadIdx.x;
    const int wid  = tid >> 5;
    const int lane = tid & 31;
    const int grp  = lane >> 2;       // 0..7: row within m16
    const int kq   = lane & 3;        // 0..3

    const int mtile = blockIdx.x >> 2;       // 0..63
    const int kh    = blockIdx.x & 3;        // 0..3

    // A lane base: row = mtile*128 + wid*16 + grp, k = kh*KH + 2*kq
    const float* Abase = A + (size_t)(mtile * BM + wid * 16 + grp) * NN + kh * KH + 2 * kq;
    // B cp.async: thread handles n = tid>>2, 16B chunk c = tid&3
    const uint16_t* Bsrc = g_YTh + (size_t)(tid >> 2) * NN + kh * KH + (tid & 3) * 8;
    const uint32_t bDst = smemU + (tid >> 2) * (BROW * 4) + (tid & 3) * 16;

    // ldmatrix per-lane addresses: x4 #j covers (nt=2j,p0),(2j,p1),(2j+1,p0),(2j+1,p1)
    uint32_t bOff[4];
    {
        int mi = lane >> 3, rw = lane & 7;
#pragma unroll
        for (int j = 0; j < 4; ++j)
            bOff[j] = smemU + (((2 * j + (mi >> 1)) * 8 + rw) * (BROW * 4)) + (mi & 1) * 16;
    }

    float acc[8][4];
#pragma unroll
    for (int t = 0; t < 8; ++t)
#pragma unroll
        for (int r = 0; r < 4; ++r) acc[t][r] = 0.0f;
    float ds0 = 0.0f, ds1 = 0.0f;

    float2 fb1[8], fb2[8];

    // prolog: B stages 0..PD-1, A tile 0
#pragma unroll
    for (int t = 0; t < PD; ++t) {
        CPA16(bDst + t * BSTG_B, Bsrc + t * 32);
        CPCOMMIT();
    }
    LDGA(fb1, 0);

    for (int i = 0; i < NT; i += 2) {
        BODY(i,     fb1, fb2);
        BODY(i + 1, fb2, fb1);
    }

    // deg: reduce over the 4 kq lanes of each (wid, grp) quad
    {
        float d0 = ds0, d1 = ds1;
        d0 += __shfl_xor_sync(0xFFFFFFFFu, d0, 1);
        d0 += __shfl_xor_sync(0xFFFFFFFFu, d0, 2);
        d1 += __shfl_xor_sync(0xFFFFFFFFu, d1, 1);
        d1 += __shfl_xor_sync(0xFFFFFFFFu, d1, 2);
        if (kq == 0) {
            int row = mtile * BM + wid * 16 + grp;
            g_degp[kh][row]     = d0;
            g_degp[kh][row + 8] = d1;
        }
    }

    // store partial T
    float* dst = g_T[kh];
    int row_lo = mtile * BM + wid * 16 + grp;
    int row_hi = row_lo + 8;
#pragma unroll
    for (int t = 0; t < 8; ++t) {
        int col = t * 8 + 2 * kq;
        *(float2*)&dst[(size_t)row_lo * OO + col] = make_float2(acc[t][0], acc[t][1]);
        *(float2*)&dst[(size_t)row_hi * OO + col] = make_float2(acc[t][2], acc[t][3]);
    }
}

// ===================== kernel 3: combine + epilogue (float4) =====================
__global__ __launch_bounds__(256) void epilogue_kernel(float* __restrict__ out) {
    int idx = blockIdx.x * blockDim.x + threadIdx.x;   // float4 index
    int r = idx >> 4;                                  // 16 float4 per row
    float deg = 1.0f;
    float4 tsum = make_float4(0.f, 0.f, 0.f, 0.f);
#pragma unroll
    for (int s = 0; s < SPLITK; ++s) {
        deg += g_degp[s][r];
        float4 v = *(const float4*)&g_T[s][(size_t)idx * 4];
        tsum.x += v.x; tsum.y += v.y; tsum.z += v.z; tsum.w += v.w;
    }
    float inv = 1.0f / deg;
    float4 xw = *(const float4*)&g_XW1[(size_t)idx * 4];
    float4 o = make_float4(xw.x + tsum.x * inv, xw.y + tsum.y * inv,
                           xw.z + tsum.z * inv, xw.w + tsum.w * inv);
    *(float4*)&out[(size_t)idx * 4] = o;
}

// -------------------- launch --------------------
extern "C" void kernel_launch(void* const* d_in, const int* in_sizes, int n_in,
                              void* d_out, int out_size) {
    const float* adj      = (const float*)d_in[0];  // [8192, 8192]
    const float* features = (const float*)d_in[1];  // [8192, 64]
    const float* W        = (const float*)d_in[2];  // [64, 128]
    float* out            = (float*)d_out;          // [8192, 64]

    cudaFuncSetAttribute(proj_kernel,
                         cudaFuncAttributeMaxDynamicSharedMemorySize, PROJ_SMEM);

    prep_w_kernel<<<32, 256>>>(W);
    proj_kernel<<<NN / 32, 256, PROJ_SMEM>>>(features);
    sage_mma_kernel<<<SPLITK * (NN / BM), 256, SMEM_MAIN>>>(adj);
    epilogue_kernel<<<(NN * OO / 4) / 256, 256>>>(out);
}

// round 12
// speedup vs baseline: 1.5515x; 1.1307x over previous
#include <cuda_runtime.h>
#include <cstdint>

#define NN 8192
#define FF 64
#define OO 64
#define BM 128
#define SPLITK 4
#define KH (NN / SPLITK)        // 2048
#define NT (KH / 32)            // 64 k-tiles per CTA

// A smem: bf16, 128 rows x 80B (16 data words + 4 pad), 3 stages
#define AROW_B 80
#define ASTG_B (BM * AROW_B)    // 10240
#define NASTG 3
// B smem: bf16, 64 rows x 80B, 5 stages, prefetch distance 4
#define BOFF   (NASTG * ASTG_B) // 30720
#define BSTG_B (64 * AROW_B)    // 5120
#define NBSTG 5
#define PD 4
#define SMEM_MAIN (BOFF + NBSTG * BSTG_B)   // 56320

// -------------------- scratch --------------------
__device__ uint16_t g_YTh[64 * NN];      // bf16 YT[n][k] = (X @ W2^T)[k][n]
__device__ float g_Wt[64 * 128];         // Wt[k][n] = W[n&63][(n>>6)*64 + k]
__device__ float g_XW1[NN * OO];         // X @ W1^T
__device__ float g_T[SPLITK][NN * OO];   // split-K partials of A @ YT^T
__device__ float g_degp[SPLITK][NN];     // split-K partials of rowsum(A)

__device__ __forceinline__ uint32_t smem_u32(const void* p) {
    uint32_t a;
    asm("{ .reg .u64 t; cvta.to.shared.u64 t, %1; cvt.u32.u64 %0, t; }" : "=r"(a) : "l"(p));
    return a;
}
__device__ __forceinline__ void mma_bf16(float* c, uint32_t a0, uint32_t a1, uint32_t a2,
                                         uint32_t a3, uint32_t b0, uint32_t b1) {
    asm volatile(
        "mma.sync.aligned.m16n8k16.row.col.f32.bf16.bf16.f32 "
        "{%0,%1,%2,%3}, {%4,%5,%6,%7}, {%8,%9}, {%0,%1,%2,%3};\n"
        : "+f"(c[0]), "+f"(c[1]), "+f"(c[2]), "+f"(c[3])
        : "r"(a0), "r"(a1), "r"(a2), "r"(a3), "r"(b0), "r"(b1));
}
#define CVT2(d, hi, lo) \
    asm("cvt.rn.bf16x2.f32 %0, %1, %2;" : "=r"(d) : "f"(hi), "f"(lo))
#define LDSM4(r0, r1, r2, r3, addr)                                              \
    asm volatile("ldmatrix.sync.aligned.m8n8.x4.shared.b16 {%0,%1,%2,%3}, [%4];" \
                 : "=r"(r0), "=r"(r1), "=r"(r2), "=r"(r3) : "r"(addr))
#define CPA16(dst, src) \
    asm volatile("cp.async.cg.shared.global [%0], [%1], 16;\n" :: "r"(dst), "l"(src))
#define CPCOMMIT() asm volatile("cp.async.commit_group;\n" ::: "memory")
#define CPWAIT(n)  asm volatile("cp.async.wait_group %0;\n" :: "n"(n) : "memory")

// ===================== kernel 0: W pre-transpose (once) =====================
__global__ void prep_w_kernel(const float* __restrict__ W) {
    int idx = blockIdx.x * 256 + threadIdx.x;   // 0..8191
    int o = idx >> 7, c = idx & 127;
    g_Wt[(c & 63) * 128 + (c >> 6) * 64 + o] = W[idx];
}

// ===================== kernel 1: projections (32 rows/block) =====================
#define WST_STRIDE 136
#define XST_STRIDE 34
#define YS_STRIDE  66
#define PROJ_SMEM ((64 * WST_STRIDE + 64 * XST_STRIDE + 32 * YS_STRIDE) * 4)

__global__ __launch_bounds__(256) void proj_kernel(const float* __restrict__ x) {
    extern __shared__ float s[];
    float* Wst = s;
    float* xst = Wst + 64 * WST_STRIDE;
    float* ys  = xst + 64 * XST_STRIDE;

    const int t  = threadIdx.x;
    const int i0 = blockIdx.x * 32;

#pragma unroll
    for (int j = 0; j < 8; ++j) {
        int idx4 = t + j * 256;
        int k = idx4 >> 5, n4 = (idx4 & 31) * 4;
        *(float4*)&Wst[k * WST_STRIDE + n4] = *(const float4*)&g_Wt[k * 128 + n4];
    }
#pragma unroll
    for (int j = 0; j < 8; ++j) {
        int idx = t + j * 256;
        int r = idx >> 6, k = idx & 63;
        xst[k * XST_STRIDE + r] = x[(size_t)(i0 + r) * FF + k];
    }
    __syncthreads();

    const int tx = t & 15;
    const int ty = t >> 4;

    float acc[2][8];
#pragma unroll
    for (int r = 0; r < 2; ++r)
#pragma unroll
        for (int j = 0; j < 8; ++j) acc[r][j] = 0.0f;

#pragma unroll
    for (int k = 0; k < 64; ++k) {
        float2 a  = *(const float2*)&xst[k * XST_STRIDE + 2 * ty];
        float4 b0 = *(const float4*)&Wst[k * WST_STRIDE + tx * 8];
        float4 b1 = *(const float4*)&Wst[k * WST_STRIDE + tx * 8 + 4];
        float av[2] = {a.x, a.y};
        float bv[8] = {b0.x, b0.y, b0.z, b0.w, b1.x, b1.y, b1.z, b1.w};
#pragma unroll
        for (int r = 0; r < 2; ++r)
#pragma unroll
            for (int j = 0; j < 8; ++j) acc[r][j] = fmaf(av[r], bv[j], acc[r][j]);
    }

    if (tx < 8) {
#pragma unroll
        for (int r = 0; r < 2; ++r) {
            size_t base = (size_t)(i0 + 2 * ty + r) * OO + tx * 8;
            *(float4*)&g_XW1[base]     = make_float4(acc[r][0], acc[r][1], acc[r][2], acc[r][3]);
            *(float4*)&g_XW1[base + 4] = make_float4(acc[r][4], acc[r][5], acc[r][6], acc[r][7]);
        }
    } else {
        int qb = (tx - 8) * 8;
#pragma unroll
        for (int r = 0; r < 2; ++r)
#pragma unroll
            for (int j = 0; j < 8; ++j)
                ys[(2 * ty + r) * YS_STRIDE + qb + j] = acc[r][j];
    }
    __syncthreads();

    {
        int col = t & 63, rb = (t >> 6) * 8;
        float v[8];
#pragma unroll
        for (int j = 0; j < 8; ++j) v[j] = ys[(rb + j) * YS_STRIDE + col];
        uint32_t u[4];
        CVT2(u[0], v[1], v[0]);
        CVT2(u[1], v[3], v[2]);
        CVT2(u[2], v[5], v[4]);
        CVT2(u[3], v[7], v[6]);
        *(uint4*)&g_YTh[(size_t)col * NN + i0 + rb] = make_uint4(u[0], u[1], u[2], u[3]);
    }
}

// ===================== kernel 2: split-K A@Y (bf16, LDSM, cp.async B) ==========
#define LDGA(buf, t_) do {                                                         \
    int k0 = (t_) * 32;                                                            \
    _Pragma("unroll")                                                              \
    for (int i_ = 0; i_ < 4; ++i_) {                                               \
        int idx = tid + i_ * 256;                                                  \
        buf[i_] = *(const float4*)(Abase + (size_t)(idx >> 3) * NN + k0 + (idx & 7) * 4); \
    }                                                                              \
} while (0)

// NOTE: pointer-based shared store (sm is the real shared array pointer)
#define STSA(buf, st) do {                                                         \
    uint2* base = (uint2*)((char*)sm + (st) * ASTG_B);                             \
    _Pragma("unroll")                                                              \
    for (int i_ = 0; i_ < 4; ++i_) {                                               \
        float4 v = buf[i_];                                                        \
        int idx = tid + i_ * 256;                                                  \
        dsum[i_] += (v.x + v.y) + (v.z + v.w);                                     \
        uint32_t lo, hi;                                                           \
        CVT2(lo, v.y, v.x); CVT2(hi, v.w, v.z);                                    \
        base[(idx >> 3) * 10 + (idx & 7)] = make_uint2(lo, hi);                    \
    }                                                                              \
} while (0)

#define MMA_STAGE(st) do {                                                         \
    uint32_t aB = aAddr + ((st) % NASTG) * ASTG_B;                                 \
    uint32_t bS = ((st) % NBSTG) * BSTG_B;                                         \
    _Pragma("unroll")                                                              \
    for (int s_ = 0; s_ < 2; ++s_) {                                               \
        uint32_t a_[4], b_[16];                                                    \
        LDSM4(a_[0], a_[1], a_[2], a_[3], aB + s_ * 32);                           \
        LDSM4(b_[0],  b_[1],  b_[2],  b_[3],  bOff[0] + bS + s_ * 32);             \
        LDSM4(b_[4],  b_[5],  b_[6],  b_[7],  bOff[1] + bS + s_ * 32);             \
        LDSM4(b_[8],  b_[9],  b_[10], b_[11], bOff[2] + bS + s_ * 32);             \
        LDSM4(b_[12], b_[13], b_[14], b_[15], bOff[3] + bS + s_ * 32);             \
        _Pragma("unroll")                                                          \
        for (int nt_ = 0; nt_ < 8; ++nt_)                                          \
            mma_bf16(acc[nt_], a_[0], a_[1], a_[2], a_[3],                         \
                     b_[(nt_ >> 1) * 4 + (nt_ & 1) * 2],                           \
                     b_[(nt_ >> 1) * 4 + (nt_ & 1) * 2 + 1]);                      \
    }                                                                              \
} while (0)

#define BODY(i_, FBX, FBY) do {                                                    \
    if ((i_) + 2 < NT) LDGA(FBX, (i_) + 2);                                        \
    CPWAIT(3);                                                                     \
    __syncthreads();                                                               \
    if ((i_) + PD < NT)                                                            \
        CPA16(bDst + (((i_) + PD) % NBSTG) * BSTG_B, Bsrc + ((i_) + PD) * 32);     \
    CPCOMMIT();                                                                    \
    MMA_STAGE(i_);                                                                 \
    if ((i_) + 1 < NT) STSA(FBY, ((i_) + 1) % NASTG);                              \
} while (0)

__global__ __launch_bounds__(256, 2) void sage_mma_kernel(const float* __restrict__ A) {
    extern __shared__ uint32_t sm[];
    const uint32_t smA = smem_u32(sm);
    const int tid  = threadIdx.x;
    const int wid  = tid >> 5;
    const int lane = tid & 31;
    const int grp  = lane >> 2;
    const int kq   = lane & 3;
    const int m0   = wid * 16;

    const int mtile = blockIdx.x >> 2;
    const int kh    = blockIdx.x & 3;

    const float* Abase = A + (size_t)(mtile * BM) * NN + kh * KH;
    const uint16_t* Bsrc = g_YTh + (size_t)(tid >> 2) * NN + kh * KH + (tid & 3) * 8;
    const uint32_t bDst = smA + BOFF + (tid >> 2) * AROW_B + (tid & 3) * 16;

    // LDSM addresses
    const uint32_t aAddr = smA + (m0 + (lane & 15)) * AROW_B + (lane >> 4) * 16;
    uint32_t bOff[4];
    {
        int mi = lane >> 3, rw = lane & 7;
#pragma unroll
        for (int j = 0; j < 4; ++j)
            bOff[j] = smA + BOFF + ((2 * j + (mi >> 1)) * 8 + rw) * AROW_B + (mi & 1) * 16;
    }

    float acc[8][4];
#pragma unroll
    for (int t = 0; t < 8; ++t)
#pragma unroll
        for (int r = 0; r < 4; ++r) acc[t][r] = 0.0f;
    float dsum[4] = {0.f, 0.f, 0.f, 0.f};

    float4 fb1[4], fb2[4];

    // prolog: B tiles 0..PD-1 via cp.async; A tile 0 -> stage 0; A tile 1 -> regs
#pragma unroll
    for (int t = 0; t < PD; ++t) {
        CPA16(bDst + t * BSTG_B, Bsrc + t * 32);
        CPCOMMIT();
    }
    LDGA(fb1, 0);
    STSA(fb1, 0);
    LDGA(fb2, 1);

    for (int i = 0; i < NT; i += 2) {
        BODY(i,     fb1, fb2);
        BODY(i + 1, fb2, fb1);
    }

    // deg: reduce the 8 chunk-threads of each row (contiguous 8 lanes)
#pragma unroll
    for (int i = 0; i < 4; ++i) {
        float d = dsum[i];
        d += __shfl_down_sync(0xFFFFFFFFu, d, 4);
        d += __shfl_down_sync(0xFFFFFFFFu, d, 2);
        d += __shfl_down_sync(0xFFFFFFFFu, d, 1);
        if ((lane & 7) == 0)
            g_degp[kh][mtile * BM + (tid >> 3) + i * 32] = d;
    }

    // store partial T
    float* dst = g_T[kh];
    int row_lo = mtile * BM + m0 + grp;
    int row_hi = row_lo + 8;
#pragma unroll
    for (int t = 0; t < 8; ++t) {
        int col = t * 8 + 2 * kq;
        *(float2*)&dst[(size_t)row_lo * OO + col] = make_float2(acc[t][0], acc[t][1]);
        *(float2*)&dst[(size_t)row_hi * OO + col] = make_float2(acc[t][2], acc[t][3]);
    }
}

// ===================== kernel 3: combine + epilogue (float4) =====================
__global__ __launch_bounds__(256) void epilogue_kernel(float* __restrict__ out) {
    int idx = blockIdx.x * blockDim.x + threadIdx.x;   // float4 index
    int r = idx >> 4;
    float deg = 1.0f;
    float4 tsum = make_float4(0.f, 0.f, 0.f, 0.f);
#pragma unroll
    for (int s = 0; s < SPLITK; ++s) {
        deg += g_degp[s][r];
        float4 v = *(const float4*)&g_T[s][(size_t)idx * 4];
        tsum.x += v.x; tsum.y += v.y; tsum.z += v.z; tsum.w += v.w;
    }
    float inv = 1.0f / deg;
    float4 xw = *(const float4*)&g_XW1[(size_t)idx * 4];
    *(float4*)&out[(size_t)idx * 4] =
        make_float4(xw.x + tsum.x * inv, xw.y + tsum.y * inv,
                    xw.z + tsum.z * inv, xw.w + tsum.w * inv);
}

// -------------------- launch --------------------
extern "C" void kernel_launch(void* const* d_in, const int* in_sizes, int n_in,
                              void* d_out, int out_size) {
    const float* adj      = (const float*)d_in[0];  // [8192, 8192]
    const float* features = (const float*)d_in[1];  // [8192, 64]
    const float* W        = (const float*)d_in[2];  // [64, 128]
    float* out            = (float*)d_out;          // [8192, 64]

    cudaFuncSetAttribute(proj_kernel,
                         cudaFuncAttributeMaxDynamicSharedMemorySize, PROJ_SMEM);
    cudaFuncSetAttribute(sage_mma_kernel,
                         cudaFuncAttributeMaxDynamicSharedMemorySize, SMEM_MAIN);

    prep_w_kernel<<<32, 256>>>(W);
    proj_kernel<<<NN / 32, 256, PROJ_SMEM>>>(features);
    sage_mma_kernel<<<SPLITK * (NN / BM), 256, SMEM_MAIN>>>(adj);
    epilogue_kernel<<<(NN * OO / 4) / 256, 256>>>(out);
}